// round 2
// baseline (speedup 1.0000x reference)
#include <cuda_runtime.h>

typedef unsigned long long u64;

// smem layout (float offsets)
#define OFF_XD 0          // f_dem window [64ch][64px]
#define OFF_XA 4096       // f_ae window -> reused as attention output O
#define OFF_Q  8192       // Q[d][px]    -> reused as A[oc][px]
#define OFF_K  12288      // K[d][px]
#define OFF_V  16384      // V[d][px]
#define OFF_S  20480      // attn logits/probs, stride 65 (64*65 = 4160)
#define OFF_TR 24640      // trust [4][64]
#define OFF_BG 24896      // gate bias [64]
#define SMEM_FLOATS 24960
#define SMEM_BYTES (SMEM_FLOATS * 4)

__device__ __forceinline__ u64 splat2(float x) {
    u64 r; asm("mov.b64 %0,{%1,%1};" : "=l"(r) : "f"(x)); return r;
}
__device__ __forceinline__ u64 pack2(float a, float b) {
    u64 r; asm("mov.b64 %0,{%1,%2};" : "=l"(r) : "f"(a), "f"(b)); return r;
}
__device__ __forceinline__ void fma2(u64& d, u64 a, u64 b) {
    asm("fma.rn.f32x2 %0,%1,%2,%0;" : "+l"(d) : "l"(a), "l"(b));
}
__device__ __forceinline__ float2 unpk(u64 a) {
    float2 r; asm("mov.b64 {%0,%1},%2;" : "=f"(r.x), "=f"(r.y) : "l"(a)); return r;
}

// Accumulate 8 output rows (o0..o0+7) x 2 px (lane, lane+32) over KC channels.
// W: gmem row-major [rows][ws], uniform across lanes (L1-cached broadcast).
// X: smem [KC][64].
__device__ __forceinline__ void gemm8(const float* __restrict__ W, int ws, int o0,
                                      const float* __restrict__ X, int KC,
                                      int lane, u64* __restrict__ acc) {
    const float* wp = W + o0 * ws;
#pragma unroll 2
    for (int c = 0; c < KC; ++c) {
        u64 xp = pack2(X[c * 64 + lane], X[c * 64 + lane + 32]);
#pragma unroll
        for (int j = 0; j < 8; ++j)
            fma2(acc[j], splat2(wp[j * ws + c]), xp);
    }
}

__global__ void __launch_bounds__(256, 2) wca_kernel(
    const float* __restrict__ fdem, const float* __restrict__ fae,
    const float* __restrict__ trg,
    const float* __restrict__ Wq, const float* __restrict__ Wk,
    const float* __restrict__ Wv, const float* __restrict__ Wo,
    const float* __restrict__ Wg, const float* __restrict__ bg,
    const unsigned* __restrict__ alphaBits, float* __restrict__ out)
{
    extern __shared__ float sm[];
    const int tid = threadIdx.x, lane = tid & 31, warp = tid >> 5;
    const int win = blockIdx.x;
    const int b = win >> 10, wy = (win >> 5) & 31, wx = win & 31;
    const int rowbase = (wy * 8) * 256 + wx * 8;

    // ---- stage inputs into smem ----
    for (int i = tid; i < 4096; i += 256) {
        int c = i >> 6, p = i & 63;
        int g = (b * 64 + c) * 65536 + rowbase + (p >> 3) * 256 + (p & 7);
        sm[OFF_XD + i] = fdem[g];
        sm[OFF_XA + i] = fae[g];
    }
    {
        int c = tid >> 6, p = tid & 63;
        sm[OFF_TR + tid] = trg[(b * 4 + c) * 65536 + rowbase + (p >> 3) * 256 + (p & 7)];
    }
    if (tid < 64) sm[OFF_BG + tid] = bg[tid];
    __syncthreads();

    const int o0 = warp * 8;
    u64 acc[8];

    // ---- Q = Wq @ Xd ----
    for (int j = 0; j < 8; ++j) acc[j] = 0ull;
    gemm8(Wq, 64, o0, sm + OFF_XD, 64, lane, acc);
    for (int j = 0; j < 8; ++j) {
        float2 v = unpk(acc[j]);
        sm[OFF_Q + (o0 + j) * 64 + lane] = v.x;
        sm[OFF_Q + (o0 + j) * 64 + lane + 32] = v.y;
    }
    // ---- K = Wk @ Xa ----
    for (int j = 0; j < 8; ++j) acc[j] = 0ull;
    gemm8(Wk, 64, o0, sm + OFF_XA, 64, lane, acc);
    for (int j = 0; j < 8; ++j) {
        float2 v = unpk(acc[j]);
        sm[OFF_K + (o0 + j) * 64 + lane] = v.x;
        sm[OFF_K + (o0 + j) * 64 + lane + 32] = v.y;
    }
    // ---- V = Wv @ Xa ----
    for (int j = 0; j < 8; ++j) acc[j] = 0ull;
    gemm8(Wv, 64, o0, sm + OFF_XA, 64, lane, acc);
    for (int j = 0; j < 8; ++j) {
        float2 v = unpk(acc[j]);
        sm[OFF_V + (o0 + j) * 64 + lane] = v.x;
        sm[OFF_V + (o0 + j) * 64 + lane + 32] = v.y;
    }
    __syncthreads();

    // ---- attention, one head at a time ----
    for (int h = 0; h < 4; ++h) {
        const float* Qh = sm + OFF_Q + h * 16 * 64;
        const float* Kh = sm + OFF_K + h * 16 * 64;
        const float* Vh = sm + OFF_V + h * 16 * 64;

        // S[l][m] = 0.25 * sum_d Qh[d][l] * Kh[d][m]; warp owns 8 l-rows
        u64 sacc[8];
        for (int j = 0; j < 8; ++j) sacc[j] = 0ull;
#pragma unroll
        for (int d = 0; d < 16; ++d) {
            u64 kp = pack2(Kh[d * 64 + lane], Kh[d * 64 + lane + 32]);
#pragma unroll
            for (int j = 0; j < 8; ++j)
                fma2(sacc[j], splat2(Qh[d * 64 + o0 + j]), kp);
        }
        for (int j = 0; j < 8; ++j) {
            float2 v = unpk(sacc[j]);
            sm[OFF_S + (o0 + j) * 65 + lane] = v.x * 0.25f;
            sm[OFF_S + (o0 + j) * 65 + lane + 32] = v.y * 0.25f;
        }
        __syncthreads();

        // softmax rows (thread l handles row l)
        if (tid < 64) {
            float* Sr = sm + OFF_S + tid * 65;
            float mx = -1e30f;
            for (int m = 0; m < 64; ++m) mx = fmaxf(mx, Sr[m]);
            float s = 0.f;
            for (int m = 0; m < 64; ++m) { float e = __expf(Sr[m] - mx); Sr[m] = e; s += e; }
            float inv = 1.f / s;
            for (int m = 0; m < 64; ++m) Sr[m] *= inv;
        }
        __syncthreads();

        // O[hb+d][l] = sum_m Vh[d][m] * P[l][m]; warp owns 2 d-dims
        {
            int d0 = warp * 2;
            u64 a0 = 0ull, a1 = 0ull;
#pragma unroll 4
            for (int m = 0; m < 64; ++m) {
                u64 pp = pack2(sm[OFF_S + lane * 65 + m],
                               sm[OFF_S + (lane + 32) * 65 + m]);
                fma2(a0, splat2(Vh[d0 * 64 + m]), pp);
                fma2(a1, splat2(Vh[(d0 + 1) * 64 + m]), pp);
            }
            float2 v0 = unpk(a0), v1 = unpk(a1);
            float* O = sm + OFF_XA;  // Xa is dead; reuse as O
            O[(h * 16 + d0) * 64 + lane] = v0.x;
            O[(h * 16 + d0) * 64 + lane + 32] = v0.y;
            O[(h * 16 + d0 + 1) * 64 + lane] = v1.x;
            O[(h * 16 + d0 + 1) * 64 + lane + 32] = v1.y;
        }
        __syncthreads();
    }

    // ---- A = Wo @ O, into Q buffer (Q is dead) ----
    for (int j = 0; j < 8; ++j) acc[j] = 0ull;
    gemm8(Wo, 64, o0, sm + OFF_XA, 64, lane, acc);
    __syncthreads();  // everyone done reading Q-as-Q before overwrite
    for (int j = 0; j < 8; ++j) {
        float2 v = unpk(acc[j]);
        sm[OFF_Q + (o0 + j) * 64 + lane] = v.x;
        sm[OFF_Q + (o0 + j) * 64 + lane + 32] = v.y;
    }
    __syncthreads();

    // ---- gate GEMM over concat [Xd | A | trust] ----
    for (int j = 0; j < 8; ++j) acc[j] = 0ull;
    gemm8(Wg, 132, o0, sm + OFF_XD, 64, lane, acc);        // cols 0..63
    gemm8(Wg + 64, 132, o0, sm + OFF_Q, 64, lane, acc);    // cols 64..127
    gemm8(Wg + 128, 132, o0, sm + OFF_TR, 4, lane, acc);   // cols 128..131

    // alpha: accept either int32 or float32 encoding
    unsigned ab = *alphaBits;
    float alpha = (ab & 0x7f800000u) ? __uint_as_float(ab) : (float)(int)ab;

    // ---- sigmoid gate + residual + store ----
#pragma unroll
    for (int j = 0; j < 8; ++j) {
        float2 v = unpk(acc[j]);
        int o = o0 + j;
        float bias = sm[OFF_BG + o];
        float a0 = sm[OFF_Q + o * 64 + lane];
        float a1 = sm[OFF_Q + o * 64 + lane + 32];
        float x0 = sm[OFF_XD + o * 64 + lane];
        float x1 = sm[OFF_XD + o * 64 + lane + 32];
        float g0 = 1.f / (1.f + __expf(-(v.x + bias)));
        float g1 = 1.f / (1.f + __expf(-(v.y + bias)));
        int gbase = (b * 64 + o) * 65536 + rowbase;
        int l2 = lane + 32;
        out[gbase + (lane >> 3) * 256 + (lane & 7)] = x0 + alpha * g0 * a0;
        out[gbase + (l2 >> 3) * 256 + (l2 & 7)]   = x1 + alpha * g1 * a1;
    }
}

extern "C" void kernel_launch(void* const* d_in, const int* in_sizes, int n_in,
                              void* d_out, int out_size) {
    (void)in_sizes; (void)n_in; (void)out_size;
    cudaFuncSetAttribute(wca_kernel, cudaFuncAttributeMaxDynamicSharedMemorySize,
                         SMEM_BYTES);
    wca_kernel<<<8192, 256, SMEM_BYTES>>>(
        (const float*)d_in[0], (const float*)d_in[1], (const float*)d_in[2],
        (const float*)d_in[3], (const float*)d_in[4], (const float*)d_in[5],
        (const float*)d_in[6], (const float*)d_in[7], (const float*)d_in[8],
        (const unsigned*)d_in[9], (float*)d_out);
}